// round 11
// baseline (speedup 1.0000x reference)
#include <cuda_runtime.h>
#include <cuda_fp16.h>
#include <math.h>
#include <stdint.h>

// ---------------------------------------------------------------------------
// ConvKAN as conv3x3-GEMM over expanded features (silu + 6 cubic B-spline
// bases), fp16 inputs, fp32 accumulation.
//   M = 32768 pixels, N = 128 outputs, K = 9*448 = 4032
// GEMM: mma.sync.m16n8k16 + ldmatrix.x4 (SW128 swizzle) + cp.async.cg,
//   3-stage pipeline, ONE barrier per K-tile:
//     wait(own tile-kt group) -> __syncthreads -> issue tile kt+2 -> compute kt
//   The barrier after the wait publishes all threads' tile-kt data AND proves
//   compute kt-1 finished everywhere (so stage (kt+2)%3 is reusable).
// ---------------------------------------------------------------------------

#define B_      8
#define H_      64
#define W_      64
#define CIN     64
#define COUT    128
#define FEAT    7
#define CEXP    (CIN*FEAT)   // 448
#define HP      (H_+2)
#define WP      (W_+2)
#define KTOT    (9*CEXP)     // 4032
#define BKH     64           // halves per K-tile (128B rows)
#define NCH     (CEXP/BKH)   // 7 chunks per tap
#define NIT     (9*NCH)      // 63 K-tiles

__device__ __align__(128) __half g_A[(size_t)B_*HP*WP*CEXP];  // expanded (halo=f(0))
__device__ __align__(128) __half g_Wt[(size_t)COUT*KTOT];     // packed weights [o][k]

__device__ __forceinline__ uint32_t smem_u32(const void* p) {
    uint32_t a;
    asm("{ .reg .u64 t; cvta.to.shared.u64 t, %1; cvt.u32.u64 %0, t; }"
        : "=r"(a) : "l"(p));
    return a;
}
#define CP_ASYNC16(dst, src) \
    asm volatile("cp.async.cg.shared.global [%0], [%1], 16;" :: "r"(dst), "l"(src))
#define CP_COMMIT() asm volatile("cp.async.commit_group;" ::: "memory")
#define CP_WAIT(n)  asm volatile("cp.async.wait_group %0;" :: "n"(n) : "memory")
#define LDSM_X4(r, a) \
    asm volatile("ldmatrix.sync.aligned.m8n8.x4.shared.b16 {%0,%1,%2,%3}, [%4];" \
        : "=r"((r)[0]), "=r"((r)[1]), "=r"((r)[2]), "=r"((r)[3]) : "r"(a))

// ---------------------------------------------------------------------------
// Kernel 1 (fused): blocks [0, NEXP) expand x -> A; blocks [NEXP, ...) pack W.
// expand: 4 pixels x 64 channels per block, smem staging, coalesced output.
// halo pixels get features(0) (bases(0) != 0!).
// ---------------------------------------------------------------------------
#define NEXP  ((B_*HP*WP)/4)                 // 8712 expand blocks
#define NWPK  ((COUT*KTOT + 255)/256)        // 2016 wpack blocks

__global__ __launch_bounds__(256) void prep_kernel(
        const float* __restrict__ x,
        const float* __restrict__ base_w,
        const float* __restrict__ spline_w) {
    if (blockIdx.x >= NEXP) {
        // ---- weight pack: g_Wt[o][k], k = tap*448 + c*7 + t, i = c*9 + tap
        int idx = (blockIdx.x - NEXP) * 256 + threadIdx.x;
        if (idx >= COUT*KTOT) return;
        int o = idx / KTOT;
        int k = idx - o * KTOT;
        int tap = k / CEXP;
        int cc  = k - tap * CEXP;
        int c   = cc / FEAT;
        int t   = cc - c * FEAT;
        int i   = c * 9 + tap;
        float w = (t == 0) ? base_w[(size_t)o * 576 + i]
                           : spline_w[((size_t)o * 576 + i) * 6 + (t - 1)];
        g_Wt[idx] = __float2half_rn(w);
        return;
    }

    __shared__ __half st[4*CEXP];
    int t = threadIdx.x;
    int p = t >> 6, c = t & 63;
    int pix = blockIdx.x * 4 + p;
    int wp  = pix % WP;
    int t1  = pix / WP;
    int hp  = t1 % HP;
    int n   = t1 / HP;

    bool halo = (hp == 0 || hp == HP-1 || wp == 0 || wp == WP-1);
    float v = halo ? 0.0f
                   : x[(((size_t)n * H_ + (hp-1)) * W_ + (wp-1)) * CIN + c];

    float s = v / (1.0f + __expf(-v));

    __half* d = st + p * CEXP + c * FEAT;
    d[0] = __float2half_rn(s);
    d[1] = __half(0.0f); d[2] = __half(0.0f); d[3] = __half(0.0f);
    d[4] = __half(0.0f); d[5] = __half(0.0f); d[6] = __half(0.0f);

    // uniform cubic B-spline: interval j = floor((v+3)*1.5) in [0,8],
    // pieces n0..n3 land in basis slots m = j-3..j, clipped to [0,5].
    float tpos = (v + 3.0f) * 1.5f;
    float fj = floorf(tpos);
    int j = (int)fj;
    if (j >= 0 && j <= 8) {
        float u  = tpos - fj;
        float um = 1.0f - u;
        float u2 = u*u, u3 = u2*u;
        const float k6 = 1.0f/6.0f;
        float n0 = um*um*um*k6;
        float n1 = (3.0f*u3 - 6.0f*u2 + 4.0f)*k6;
        float n2 = (-3.0f*u3 + 3.0f*u2 + 3.0f*u + 1.0f)*k6;
        float n3 = u3*k6;
        int m0 = j - 3;
        if (m0     >= 0 && m0     < 6) d[1 + m0] = __float2half_rn(n0);
        if (m0 + 1 >= 0 && m0 + 1 < 6) d[2 + m0] = __float2half_rn(n1);
        if (m0 + 2 >= 0 && m0 + 2 < 6) d[3 + m0] = __float2half_rn(n2);
        if (m0 + 3 >= 0 && m0 + 3 < 6) d[4 + m0] = __float2half_rn(n3);
    }
    __syncthreads();

    const uint4* s4 = (const uint4*)st;
    uint4* d4 = (uint4*)(g_A + (size_t)blockIdx.x * 4 * CEXP);
    if (t < 224) d4[t] = s4[t];   // 4*448 halves = 224 uint4
}

// ---------------------------------------------------------------------------
// Kernel 2: fp16 HMMA GEMM, BM=128 x BN=128 x BK=64 halves.
// 3-stage smem pipeline: stage s at s*32KB (A @+0 16KB, B @+16KB).
// 128B rows, SW128 swizzle (16B unit f of row r: f ^= r&7) -> ldmatrix
// conflict-free. 8 warps = 4(m) x 2(n); warp 32x64.
// ---------------------------------------------------------------------------
#define STG(s)   ((s)*32768)
#define SMEM_TOTAL (3*32768)   // 96 KB

__global__ __launch_bounds__(256, 2) void convkan_hmma(
        const float* __restrict__ bias, float* __restrict__ out) {
    extern __shared__ char smem[];
    const uint32_t sb = smem_u32(smem);

    const int bid  = blockIdx.x;          // 0..255
    const int n    = bid >> 5;
    const int h0   = (bid & 31) << 1;     // 2 image rows
    const int tid  = threadIdx.x;
    const int warp = tid >> 5;
    const int lane = tid & 31;
    const int gid  = lane >> 2;
    const int tig  = lane & 3;
    const int wm   = (warp & 3) * 32;
    const int wn   = (warp >> 2) * 64;

    // ---- loader constants: 4 16B units per thread (A and B share row/f) ----
    const __half* aGp[4];
    const __half* bGp[4];
    uint32_t ldst[4];
    #pragma unroll
    for (int i = 0; i < 4; i++) {
        int unit = i * 256 + tid;         // 0..1023
        int row  = unit >> 3;             // 0..127
        int f    = unit & 7;              // 16B unit in 128B row
        int hl   = row >> 6, wl = row & 63;
        aGp[i] = g_A + (((size_t)(n*HP + h0 + hl)) * WP + wl) * CEXP + f * 8;
        bGp[i] = g_Wt + (size_t)row * KTOT + f * 8;
        ldst[i] = sb + row * 128 + (((uint32_t)f ^ (row & 7)) << 4);
    }

    // ---- ldmatrix lane constants ----
    const int rA   = (lane & 7) + ((lane >> 3) & 1) * 8;
    const int segA = lane >> 4;
    const uint32_t aRow = (uint32_t)(wm + rA) * 128;
    const uint32_t aXor = (uint32_t)(rA & 7) << 4;
    const int rB   = (lane & 7) + (((lane >> 4) & 1) ? 8 : 0);
    const int segB = (lane >> 3) & 1;
    const uint32_t bXor = (uint32_t)(rB & 7) << 4;

    float acc[2][8][4];
    #pragma unroll
    for (int mt = 0; mt < 2; mt++)
        #pragma unroll
        for (int nt = 0; nt < 8; nt++)
            #pragma unroll
            for (int q = 0; q < 4; q++) acc[mt][nt][q] = 0.0f;

    // ---- prologue: issue tiles 0 and 1 into stages 0, 1 ----
    #pragma unroll
    for (int i = 0; i < 4; i++) {                 // tile 0: tap0,ct0
        CP_ASYNC16(ldst[i] + STG(0), aGp[i]);
        CP_ASYNC16(ldst[i] + STG(0) + 16384, bGp[i]);
    }
    CP_COMMIT();
    #pragma unroll
    for (int i = 0; i < 4; i++) {                 // tile 1: tap0,ct1
        CP_ASYNC16(ldst[i] + STG(1), aGp[i] + BKH);
        CP_ASYNC16(ldst[i] + STG(1) + 16384, bGp[i] + BKH);
    }
    CP_COMMIT();

    // counters at tile 1's state; incremented at loop top -> tile kt+2
    int tap = 0, ct = 1, kh = 0, kw = 0;
    int stage = 0;

    for (int kt = 0; kt < NIT; ++kt) {
        // 1) own group for tile kt complete (issued 2 iterations ago).
        CP_WAIT(1);
        // 2) barrier: (a) every thread passed its wait -> all threads'
        //    tile-kt data visible; (b) all threads finished compute kt-1
        //    (program order) -> stage (kt+2)%3 safe to overwrite.
        __syncthreads();

        // 3) issue tile kt+2 (overlaps with compute below).
        if (kt + 2 < NIT) {
            if (++ct == NCH) { ct = 0; ++tap; if (++kw == 3) { kw = 0; ++kh; } }
            const int koffA = (kh * WP + kw) * CEXP + ct * BKH;
            const int koffB = tap * CEXP + ct * BKH;
            const int ns = STG((stage + 2) % 3);
            #pragma unroll
            for (int i = 0; i < 4; i++) {
                CP_ASYNC16(ldst[i] + ns, aGp[i] + koffA);
                CP_ASYNC16(ldst[i] + ns + 16384, bGp[i] + koffB);
            }
        }
        CP_COMMIT();   // exactly one group per iteration (possibly empty)

        // 4) compute tile kt.
        const uint32_t Ab = sb + STG(stage);
        const uint32_t Bb = Ab + 16384;

        #pragma unroll
        for (int kk = 0; kk < 4; ++kk) {
            uint32_t afr[2][4];
            #pragma unroll
            for (int mt = 0; mt < 2; mt++) {
                uint32_t addr = Ab + aRow + mt * 2048
                              + (((uint32_t)(kk * 32 + segA * 16)) ^ aXor);
                LDSM_X4(afr[mt], addr);
            }
            uint32_t bfr[4][4];
            #pragma unroll
            for (int np = 0; np < 4; np++) {
                uint32_t addr = Bb + (uint32_t)(wn + np * 16 + rB) * 128
                              + (((uint32_t)(kk * 32 + segB * 16)) ^ bXor);
                LDSM_X4(bfr[np], addr);
            }
            #pragma unroll
            for (int np = 0; np < 4; np++)
                #pragma unroll
                for (int u = 0; u < 2; u++) {
                    const uint32_t bb0 = bfr[np][u * 2];
                    const uint32_t bb1 = bfr[np][u * 2 + 1];
                    #pragma unroll
                    for (int mt = 0; mt < 2; mt++) {
                        float* d = acc[mt][np * 2 + u];
                        asm volatile(
                            "mma.sync.aligned.m16n8k16.row.col.f32.f16.f16.f32 "
                            "{%0,%1,%2,%3}, {%4,%5,%6,%7}, {%8,%9}, {%0,%1,%2,%3};\n"
                            : "+f"(d[0]), "+f"(d[1]), "+f"(d[2]), "+f"(d[3])
                            : "r"(afr[mt][0]), "r"(afr[mt][1]),
                              "r"(afr[mt][2]), "r"(afr[mt][3]),
                              "r"(bb0), "r"(bb1));
                    }
                }
        }
        stage = (stage + 1) % 3;
    }

    // ---- epilogue: D frag (gid,tig): rows gid,gid+8; cols 2tig,2tig+1 ----
    #pragma unroll
    for (int nt = 0; nt < 8; nt++) {
        int col = wn + nt * 8 + tig * 2;
        float bx = bias[col], by = bias[col + 1];
        #pragma unroll
        for (int mt = 0; mt < 2; mt++) {
            int row0 = bid * 128 + wm + mt * 16 + gid;
            float2 v0 = make_float2(acc[mt][nt][0] + bx, acc[mt][nt][1] + by);
            float2 v1 = make_float2(acc[mt][nt][2] + bx, acc[mt][nt][3] + by);
            *(float2*)(out + (size_t)row0 * COUT + col)       = v0;
            *(float2*)(out + (size_t)(row0 + 8) * COUT + col) = v1;
        }
    }
}

// ---------------------------------------------------------------------------
extern "C" void kernel_launch(void* const* d_in, const int* in_sizes, int n_in,
                              void* d_out, int out_size) {
    const float* x        = (const float*)d_in[0];
    const float* base_w   = (const float*)d_in[1];
    const float* spline_w = (const float*)d_in[2];
    const float* bias     = (const float*)d_in[3];
    float* out = (float*)d_out;

    prep_kernel<<<NEXP + NWPK, 256>>>(x, base_w, spline_w);
    cudaFuncSetAttribute(convkan_hmma,
                         cudaFuncAttributeMaxDynamicSharedMemorySize, SMEM_TOTAL);
    convkan_hmma<<<256, 256, SMEM_TOTAL>>>(bias, out);
}

// round 12
// speedup vs baseline: 1.0443x; 1.0443x over previous
#include <cuda_runtime.h>
#include <cuda_fp16.h>
#include <math.h>
#include <stdint.h>

// ---------------------------------------------------------------------------
// ConvKAN as conv3x3-GEMM over expanded features (silu + 6 cubic B-spline
// bases), fp16 inputs, fp32 accumulation.
//   M = 32768 pixels, N = 128 outputs, K = 9*448 = 4032
// GEMM: mma.sync.m16n8k16 + ldmatrix.x4 (SW128 swizzle) + cp.async.cg,
//   3-stage pipeline. Balanced split-K: 296 CTAs (2/SM), each takes an equal
//   slice of the 256x63 (tile x K-chunk) work grid; partials combined with
//   red.global.add.f32 into a zero-initialized output.
// ---------------------------------------------------------------------------

#define B_      8
#define H_      64
#define W_      64
#define CIN     64
#define COUT    128
#define FEAT    7
#define CEXP    (CIN*FEAT)   // 448
#define HP      (H_+2)
#define WP      (W_+2)
#define KTOT    (9*CEXP)     // 4032
#define BKH     64           // halves per K-tile (128B rows)
#define NCH     (CEXP/BKH)   // 7 chunks per tap
#define NIT     (9*NCH)      // 63 K-tiles per output tile
#define NTILE   256          // output tiles (128 pixels x 128 outputs)
#define NCTA    296          // 2 CTAs per SM, exactly one wave
#define NU      (NTILE*NIT)  // 16128 work units

__device__ __align__(128) __half g_A[(size_t)B_*HP*WP*CEXP];  // expanded (halo=f(0))
__device__ __align__(128) __half g_Wt[(size_t)COUT*KTOT];     // packed weights [o][k]

__device__ __forceinline__ uint32_t smem_u32(const void* p) {
    uint32_t a;
    asm("{ .reg .u64 t; cvta.to.shared.u64 t, %1; cvt.u32.u64 %0, t; }"
        : "=r"(a) : "l"(p));
    return a;
}
#define CP_ASYNC16(dst, src) \
    asm volatile("cp.async.cg.shared.global [%0], [%1], 16;" :: "r"(dst), "l"(src))
#define CP_COMMIT() asm volatile("cp.async.commit_group;" ::: "memory")
#define CP_WAIT(n)  asm volatile("cp.async.wait_group %0;" :: "n"(n) : "memory")
#define LDSM_X4(r, a) \
    asm volatile("ldmatrix.sync.aligned.m8n8.x4.shared.b16 {%0,%1,%2,%3}, [%4];" \
        : "=r"((r)[0]), "=r"((r)[1]), "=r"((r)[2]), "=r"((r)[3]) : "r"(a))
#define RED_ADD_F32(p, v) \
    asm volatile("red.global.add.f32 [%0], %1;" :: "l"(p), "f"(v) : "memory")

// ---------------------------------------------------------------------------
// Kernel 1 (fused): [0,NEXP) expand x->A; [NEXP,NEXP+NWPK) pack W;
// [NEXP+NWPK, +NZERO) zero the output (split-K partials are red.add-ed).
// ---------------------------------------------------------------------------
#define NEXP  ((B_*HP*WP)/4)                 // 8712 expand blocks
#define NWPK  ((COUT*KTOT + 255)/256)        // 2016 wpack blocks
#define NZERO ((32768*COUT/4)/256)           // 4096 zero blocks (float4 each)

__global__ __launch_bounds__(256) void prep_kernel(
        const float* __restrict__ x,
        const float* __restrict__ base_w,
        const float* __restrict__ spline_w,
        float* __restrict__ out) {
    if (blockIdx.x >= NEXP + NWPK) {
        int idx = (blockIdx.x - NEXP - NWPK) * 256 + threadIdx.x;
        ((float4*)out)[idx] = make_float4(0.f, 0.f, 0.f, 0.f);
        return;
    }
    if (blockIdx.x >= NEXP) {
        // ---- weight pack: g_Wt[o][k], k = tap*448 + c*7 + t, i = c*9 + tap
        int idx = (blockIdx.x - NEXP) * 256 + threadIdx.x;
        if (idx >= COUT*KTOT) return;
        int o = idx / KTOT;
        int k = idx - o * KTOT;
        int tap = k / CEXP;
        int cc  = k - tap * CEXP;
        int c   = cc / FEAT;
        int t   = cc - c * FEAT;
        int i   = c * 9 + tap;
        float w = (t == 0) ? base_w[(size_t)o * 576 + i]
                           : spline_w[((size_t)o * 576 + i) * 6 + (t - 1)];
        g_Wt[idx] = __float2half_rn(w);
        return;
    }

    __shared__ __half st[4*CEXP];
    int t = threadIdx.x;
    int p = t >> 6, c = t & 63;
    int pix = blockIdx.x * 4 + p;
    int wp  = pix % WP;
    int t1  = pix / WP;
    int hp  = t1 % HP;
    int n   = t1 / HP;

    bool halo = (hp == 0 || hp == HP-1 || wp == 0 || wp == WP-1);
    float v = halo ? 0.0f
                   : x[(((size_t)n * H_ + (hp-1)) * W_ + (wp-1)) * CIN + c];

    float s = v / (1.0f + __expf(-v));

    __half* d = st + p * CEXP + c * FEAT;
    d[0] = __float2half_rn(s);
    d[1] = __half(0.0f); d[2] = __half(0.0f); d[3] = __half(0.0f);
    d[4] = __half(0.0f); d[5] = __half(0.0f); d[6] = __half(0.0f);

    // uniform cubic B-spline: interval j = floor((v+3)*1.5) in [0,8],
    // pieces n0..n3 -> basis slots m = j-3..j, clipped to [0,5].
    float tpos = (v + 3.0f) * 1.5f;
    float fj = floorf(tpos);
    int j = (int)fj;
    if (j >= 0 && j <= 8) {
        float u  = tpos - fj;
        float um = 1.0f - u;
        float u2 = u*u, u3 = u2*u;
        const float k6 = 1.0f/6.0f;
        float n0 = um*um*um*k6;
        float n1 = (3.0f*u3 - 6.0f*u2 + 4.0f)*k6;
        float n2 = (-3.0f*u3 + 3.0f*u2 + 3.0f*u + 1.0f)*k6;
        float n3 = u3*k6;
        int m0 = j - 3;
        if (m0     >= 0 && m0     < 6) d[1 + m0] = __float2half_rn(n0);
        if (m0 + 1 >= 0 && m0 + 1 < 6) d[2 + m0] = __float2half_rn(n1);
        if (m0 + 2 >= 0 && m0 + 2 < 6) d[3 + m0] = __float2half_rn(n2);
        if (m0 + 3 >= 0 && m0 + 3 < 6) d[4 + m0] = __float2half_rn(n3);
    }
    __syncthreads();

    const uint4* s4 = (const uint4*)st;
    uint4* d4 = (uint4*)(g_A + (size_t)blockIdx.x * 4 * CEXP);
    if (t < 224) d4[t] = s4[t];   // 4*448 halves = 224 uint4
}

// ---------------------------------------------------------------------------
// Kernel 2: fp16 HMMA GEMM, BM=128 x BN=128 x BK=64, balanced split-K.
// 3-stage smem pipeline: stage s at s*32KB (A @+0 16KB, B @+16KB).
// Pipeline invariant: prologue commits exactly 2 groups (2nd may be empty),
// each loop iteration commits exactly 1 (maybe empty) -> CP_WAIT(1) at iter
// kt always means "tile kt landed". __syncthreads at segment start makes
// stages reusable across segments.
// ---------------------------------------------------------------------------
#define STG(s)   ((s)*32768)
#define SMEM_TOTAL (3*32768)   // 96 KB

__global__ __launch_bounds__(256, 2) void convkan_hmma(
        const float* __restrict__ bias, float* __restrict__ out) {
    extern __shared__ char smem[];
    const uint32_t sb = smem_u32(smem);

    const int bid  = blockIdx.x;          // 0..295
    const int tid  = threadIdx.x;
    const int warp = tid >> 5;
    const int lane = tid & 31;
    const int gid  = lane >> 2;
    const int tig  = lane & 3;
    const int wm   = (warp & 3) * 32;
    const int wn   = (warp >> 2) * 64;

    // ---- loader constants: 4 16B units per thread ----
    int   aOff[4];                        // per-thread A offset within tile
    const __half* bGp[4];
    uint32_t ldst[4];
    #pragma unroll
    for (int i = 0; i < 4; i++) {
        int unit = i * 256 + tid;         // 0..1023
        int row  = unit >> 3;             // 0..127
        int f    = unit & 7;              // 16B unit in 128B row
        int hl   = row >> 6, wl = row & 63;
        aOff[i] = (hl * WP + wl) * CEXP + f * 8;
        bGp[i]  = g_Wt + (size_t)row * KTOT + f * 8;
        ldst[i] = sb + row * 128 + (((uint32_t)f ^ (row & 7)) << 4);
    }

    // ---- ldmatrix lane constants ----
    const int rA   = (lane & 7) + ((lane >> 3) & 1) * 8;
    const int segA = lane >> 4;
    const uint32_t aRow = (uint32_t)rA * 128;
    const uint32_t aXor = (uint32_t)(rA & 7) << 4;
    const int rB   = (lane & 7) + (((lane >> 4) & 1) ? 8 : 0);
    const int segB = (lane >> 3) & 1;
    const uint32_t bXor = (uint32_t)(rB & 7) << 4;

    int u0 = (bid * NU) / NCTA;
    const int u1 = ((bid + 1) * NU) / NCTA;

    while (u0 < u1) {
        const int tile = u0 / NIT;
        const int kt0  = u0 - tile * NIT;
        const int kend = min(u1 - tile * NIT, NIT);
        const int tn_  = tile >> 5;
        const int th0  = (tile & 31) << 1;
        const __half* aBase = g_A + (size_t)(tn_ * HP + th0) * WP * CEXP;

        __syncthreads();   // all threads done with previous segment's stages

        float acc[2][8][4];
        #pragma unroll
        for (int mt = 0; mt < 2; mt++)
            #pragma unroll
            for (int nt = 0; nt < 8; nt++)
                #pragma unroll
                for (int q = 0; q < 4; q++) acc[mt][nt][q] = 0.0f;

        // ---- prologue: tiles kt0 (stage0) and kt0+1 (stage1) ----
        {
            int tap = kt0 / NCH, ct = kt0 - tap * NCH;
            int koffA = ((tap / 3) * WP + (tap % 3)) * CEXP + ct * BKH;
            int koffB = tap * CEXP + ct * BKH;
            #pragma unroll
            for (int i = 0; i < 4; i++) {
                CP_ASYNC16(ldst[i] + STG(0), aBase + aOff[i] + koffA);
                CP_ASYNC16(ldst[i] + STG(0) + 16384, bGp[i] + koffB);
            }
        }
        CP_COMMIT();
        if (kt0 + 1 < kend) {
            int k1 = kt0 + 1;
            int tap = k1 / NCH, ct = k1 - tap * NCH;
            int koffA = ((tap / 3) * WP + (tap % 3)) * CEXP + ct * BKH;
            int koffB = tap * CEXP + ct * BKH;
            #pragma unroll
            for (int i = 0; i < 4; i++) {
                CP_ASYNC16(ldst[i] + STG(1), aBase + aOff[i] + koffA);
                CP_ASYNC16(ldst[i] + STG(1) + 16384, bGp[i] + koffB);
            }
        }
        CP_COMMIT();       // possibly empty -> invariant holds

        int stage = 0;
        for (int kt = kt0; kt < kend; ++kt) {
            CP_WAIT(1);        // own group for tile kt complete
            __syncthreads();   // publish all threads' tile-kt data; compute
                               // kt-1 done -> stage (stage+2)%3 reusable

            if (kt + 2 < kend) {
                int kn = kt + 2;
                int tap = kn / NCH, ct = kn - tap * NCH;
                int koffA = ((tap / 3) * WP + (tap % 3)) * CEXP + ct * BKH;
                int koffB = tap * CEXP + ct * BKH;
                const int ns = STG((stage + 2) % 3);
                #pragma unroll
                for (int i = 0; i < 4; i++) {
                    CP_ASYNC16(ldst[i] + ns, aBase + aOff[i] + koffA);
                    CP_ASYNC16(ldst[i] + ns + 16384, bGp[i] + koffB);
                }
            }
            CP_COMMIT();   // exactly one group per iteration

            const uint32_t Ab = sb + STG(stage);
            const uint32_t Bb = Ab + 16384;

            #pragma unroll
            for (int kk = 0; kk < 4; ++kk) {
                uint32_t afr[2][4];
                #pragma unroll
                for (int mt = 0; mt < 2; mt++) {
                    uint32_t addr = Ab + aRow + (uint32_t)(wm + mt * 16) * 128
                                  + (((uint32_t)(kk * 32 + segA * 16)) ^ aXor);
                    LDSM_X4(afr[mt], addr);
                }
                uint32_t bfr[4][4];
                #pragma unroll
                for (int np = 0; np < 4; np++) {
                    uint32_t addr = Bb + (uint32_t)(wn + np * 16 + rB) * 128
                                  + (((uint32_t)(kk * 32 + segB * 16)) ^ bXor);
                    LDSM_X4(bfr[np], addr);
                }
                #pragma unroll
                for (int np = 0; np < 4; np++)
                    #pragma unroll
                    for (int u = 0; u < 2; u++) {
                        const uint32_t bb0 = bfr[np][u * 2];
                        const uint32_t bb1 = bfr[np][u * 2 + 1];
                        #pragma unroll
                        for (int mt = 0; mt < 2; mt++) {
                            float* d = acc[mt][np * 2 + u];
                            asm volatile(
                                "mma.sync.aligned.m16n8k16.row.col.f32.f16.f16.f32 "
                                "{%0,%1,%2,%3}, {%4,%5,%6,%7}, {%8,%9}, {%0,%1,%2,%3};\n"
                                : "+f"(d[0]), "+f"(d[1]), "+f"(d[2]), "+f"(d[3])
                                : "r"(afr[mt][0]), "r"(afr[mt][1]),
                                  "r"(afr[mt][2]), "r"(afr[mt][3]),
                                  "r"(bb0), "r"(bb1));
                        }
                    }
            }
            stage = (stage + 1) % 3;
        }

        // ---- segment epilogue: red.add partials (bias once per tile) ----
        const float bsc = (kt0 == 0) ? 1.0f : 0.0f;
        #pragma unroll
        for (int nt = 0; nt < 8; nt++) {
            int col = wn + nt * 8 + tig * 2;
            float bx = bias[col] * bsc, by = bias[col + 1] * bsc;
            #pragma unroll
            for (int mt = 0; mt < 2; mt++) {
                int row0 = tile * 128 + wm + mt * 16 + gid;
                float* p0 = out + (size_t)row0 * COUT + col;
                float* p1 = out + (size_t)(row0 + 8) * COUT + col;
                RED_ADD_F32(p0,     acc[mt][nt][0] + bx);
                RED_ADD_F32(p0 + 1, acc[mt][nt][1] + by);
                RED_ADD_F32(p1,     acc[mt][nt][2] + bx);
                RED_ADD_F32(p1 + 1, acc[mt][nt][3] + by);
            }
        }

        u0 = tile * NIT + kend;
    }
}

// ---------------------------------------------------------------------------
extern "C" void kernel_launch(void* const* d_in, const int* in_sizes, int n_in,
                              void* d_out, int out_size) {
    const float* x        = (const float*)d_in[0];
    const float* base_w   = (const float*)d_in[1];
    const float* spline_w = (const float*)d_in[2];
    const float* bias     = (const float*)d_in[3];
    float* out = (float*)d_out;

    prep_kernel<<<NEXP + NWPK + NZERO, 256>>>(x, base_w, spline_w, out);
    cudaFuncSetAttribute(convkan_hmma,
                         cudaFuncAttributeMaxDynamicSharedMemorySize, SMEM_TOTAL);
    convkan_hmma<<<NCTA, 256, SMEM_TOTAL>>>(bias, out);
}